// round 3
// baseline (speedup 1.0000x reference)
#include <cuda_runtime.h>
#include <math.h>

#define N_NODES 50000
#define N_EDGES 500000
#define E2 (N_EDGES + N_NODES)   // edges + self loops = 550000
#define IN_DIM 128
#define F1 256
#define HH1 4
#define CC1 64
#define F2 64
#define HH2 1
#define CC2 64

// ---------------- scratch (static device globals; no allocation) ----------------
__device__ float    g_h1[(size_t)N_NODES * F1];     // x @ W1
__device__ float    g_out1[(size_t)N_NODES * F1];   // layer-1 aggregate -> elu -> layer-2 input
__device__ float    g_h2[(size_t)N_NODES * F2];     // out1 @ W2
__device__ float    g_ssrc1[N_NODES * HH1];
__device__ float    g_sdst1[N_NODES * HH1];
__device__ float    g_ssrc2[N_NODES * HH2];
__device__ float    g_sdst2[N_NODES * HH2];
__device__ unsigned g_m1[N_NODES * HH1];
__device__ float    g_den1[N_NODES * HH1];
__device__ unsigned g_m2[N_NODES * HH2];
__device__ float    g_den2[N_NODES * HH2];
__device__ float    g_alpha1[(size_t)E2 * HH1];
__device__ float    g_alpha2[(size_t)E2 * HH2];
__device__ float    g_loop[N_NODES];
__device__ float    g_cnt[N_NODES];
__device__ float    g_asum[N_NODES];
__device__ float    g_ce1[HH1];
__device__ float    g_ce2[HH2];

// ---------------- helpers ----------------
__device__ __forceinline__ unsigned enc_f(float f) {
    unsigned u = __float_as_uint(f);
    return (u & 0x80000000u) ? ~u : (u | 0x80000000u);
}
__device__ __forceinline__ float dec_f(unsigned e) {
    unsigned b = (e & 0x80000000u) ? (e ^ 0x80000000u) : ~e;
    return __uint_as_float(b);
}

// ---------------- init kernels ----------------
__global__ void init_pre(float* cnt, float* asum) {
    int i = blockIdx.x * blockDim.x + threadIdx.x;
    if (i < N_NODES) { cnt[i] = 0.f; asum[i] = 0.f; }
}

__global__ void init_layer(float* acc, int acc_n4, unsigned* m, float* den, int nh) {
    int i = blockIdx.x * blockDim.x + threadIdx.x;
    if (i < acc_n4) ((float4*)acc)[i] = make_float4(0.f, 0.f, 0.f, 0.f);
    if (i < nh) { m[i] = 0u; den[i] = 0.f; }
}

// ---------------- self-loop attr (PyG fill_value='mean') ----------------
__global__ void edge_stats(const int* __restrict__ ei, const float* __restrict__ ea,
                           float* __restrict__ cnt, float* __restrict__ asum) {
    int j = blockIdx.x * blockDim.x + threadIdx.x;
    if (j >= N_EDGES) return;
    int d = ei[N_EDGES + j];
    atomicAdd(&cnt[d], 1.f);
    atomicAdd(&asum[d], ea[j]);
}

__global__ void loop_attr_kernel(const float* __restrict__ cnt, const float* __restrict__ asum,
                                 float* __restrict__ la) {
    int i = blockIdx.x * blockDim.x + threadIdx.x;
    if (i < N_NODES) la[i] = asum[i] / fmaxf(cnt[i], 1.f);
}

// ---------------- GEMM: C[M, NC] = A[M, K] @ B[K, NC], fp32, 64x64 tile ----------------
template <int K, int NC>
__global__ void gemm_kernel(const float* __restrict__ A, const float* __restrict__ B,
                            float* __restrict__ C) {
    __shared__ float As[64][65];  // [k][m], padded against bank conflicts
    __shared__ float Bs[64][64];  // [k][c]

    const int base  = blockIdx.x * 64;
    const int cbase = blockIdx.y * 64;
    const int tid   = threadIdx.x;
    const int r0 = (tid >> 4) * 4;
    const int c0 = (tid & 15) * 4;

    float acc[4][4] = {};

    for (int kc = 0; kc < K; kc += 64) {
        #pragma unroll
        for (int idx = tid; idx < 4096; idx += 256) {
            int k = idx & 63, mm = idx >> 6;
            int gm = base + mm;
            As[k][mm] = (gm < N_NODES) ? A[(size_t)gm * K + kc + k] : 0.f;
        }
        #pragma unroll
        for (int idx = tid; idx < 4096; idx += 256) {
            int c = idx & 63, k = idx >> 6;
            Bs[k][c] = B[(size_t)(kc + k) * NC + cbase + c];
        }
        __syncthreads();
        #pragma unroll 8
        for (int k = 0; k < 64; k++) {
            float a0 = As[k][r0 + 0], a1 = As[k][r0 + 1];
            float a2 = As[k][r0 + 2], a3 = As[k][r0 + 3];
            float4 b = *(const float4*)&Bs[k][c0];
            acc[0][0] += a0 * b.x; acc[0][1] += a0 * b.y; acc[0][2] += a0 * b.z; acc[0][3] += a0 * b.w;
            acc[1][0] += a1 * b.x; acc[1][1] += a1 * b.y; acc[1][2] += a1 * b.z; acc[1][3] += a1 * b.w;
            acc[2][0] += a2 * b.x; acc[2][1] += a2 * b.y; acc[2][2] += a2 * b.z; acc[2][3] += a2 * b.w;
            acc[3][0] += a3 * b.x; acc[3][1] += a3 * b.y; acc[3][2] += a3 * b.z; acc[3][3] += a3 * b.w;
        }
        __syncthreads();
    }

    #pragma unroll
    for (int i = 0; i < 4; i++) {
        int gm = base + r0 + i;
        if (gm < N_NODES) {
            *(float4*)&C[(size_t)gm * NC + cbase + c0] =
                make_float4(acc[i][0], acc[i][1], acc[i][2], acc[i][3]);
        }
    }
}

// ---------------- per-node attention scores: ssrc[n,h] = sum_c h[n,h,c]*a_src[h,c] ----------------
template <int H, int C>
__global__ void score_kernel(const float* __restrict__ h, const float* __restrict__ a_src,
                             const float* __restrict__ a_dst,
                             float* __restrict__ ssrc, float* __restrict__ sdst) {
    const int F = H * C;
    const int PER = F / 32;
    const int G = 32 / H;  // lanes per head
    int node = (blockIdx.x * blockDim.x + threadIdx.x) >> 5;
    int lane = threadIdx.x & 31;
    if (node >= N_NODES) return;

    float ps = 0.f, pd = 0.f;
    #pragma unroll
    for (int j = 0; j < PER; j++) {
        int f = lane * PER + j;
        float hv = h[(size_t)node * F + f];
        ps += hv * a_src[f];
        pd += hv * a_dst[f];
    }
    #pragma unroll
    for (int off = G / 2; off > 0; off >>= 1) {
        ps += __shfl_xor_sync(0xFFFFFFFFu, ps, off);
        pd += __shfl_xor_sync(0xFFFFFFFFu, pd, off);
    }
    if ((lane & (G - 1)) == 0) {
        int hd = lane / G;
        ssrc[node * H + hd] = ps;
        sdst[node * H + hd] = pd;
    }
}

// ---------------- ce[h] = dot(We[h*C..], ae[h*C..]) ----------------
template <int H, int C>
__global__ void ce_kernel(const float* __restrict__ We, const float* __restrict__ ae,
                          float* __restrict__ ce) {
    int h = threadIdx.x >> 5;
    int lane = threadIdx.x & 31;
    float s = 0.f;
    for (int c = lane; c < C; c += 32) s += We[h * C + c] * ae[h * C + c];
    #pragma unroll
    for (int off = 16; off > 0; off >>= 1) s += __shfl_xor_sync(0xFFFFFFFFu, s, off);
    if (lane == 0) ce[h] = s;
}

// ---------------- edge pass A: alpha + segment max ----------------
template <int H>
__global__ void edge_max(const int* __restrict__ ei, const float* __restrict__ ea,
                         const float* __restrict__ ssrc, const float* __restrict__ sdst,
                         const float* __restrict__ ce, const float* __restrict__ la,
                         float* __restrict__ alpha, unsigned* __restrict__ m) {
    int j = blockIdx.x * blockDim.x + threadIdx.x;
    if (j >= E2) return;
    int s, d; float a;
    if (j < N_EDGES) { s = ei[j]; d = ei[N_EDGES + j]; a = ea[j]; }
    else             { s = d = j - N_EDGES; a = la[s]; }
    #pragma unroll
    for (int h = 0; h < H; h++) {
        float v = ssrc[s * H + h] + sdst[d * H + h] + a * ce[h];
        v = (v >= 0.f) ? v : 0.2f * v;  // leaky_relu(0.2)
        alpha[(size_t)j * H + h] = v;
        atomicMax(&m[d * H + h], enc_f(v));
    }
}

// ---------------- edge pass B: w = exp(alpha - m[dst]); denom += w ----------------
template <int H>
__global__ void edge_sumexp(const int* __restrict__ ei, float* __restrict__ alpha,
                            const unsigned* __restrict__ m, float* __restrict__ den) {
    int j = blockIdx.x * blockDim.x + threadIdx.x;
    if (j >= E2) return;
    int d = (j < N_EDGES) ? ei[N_EDGES + j] : (j - N_EDGES);
    #pragma unroll
    for (int h = 0; h < H; h++) {
        float w = __expf(alpha[(size_t)j * H + h] - dec_f(m[d * H + h]));
        alpha[(size_t)j * H + h] = w;
        atomicAdd(&den[d * H + h], w);
    }
}

// ---------------- edge pass C: out[dst] += (w/den) * h[src]  (warp per edge) ----------------
template <int H, int C>
__global__ void edge_agg(const int* __restrict__ ei, const float* __restrict__ w,
                         const float* __restrict__ den, const float* __restrict__ hsrc,
                         float* __restrict__ out) {
    const int F = H * C;
    const int PER = F / 32;
    int wid = (blockIdx.x * blockDim.x + threadIdx.x) >> 5;
    if (wid >= E2) return;
    int lane = threadIdx.x & 31;
    int s, d;
    if (wid < N_EDGES) { s = ei[wid]; d = ei[N_EDGES + wid]; }
    else               { s = d = wid - N_EDGES; }
    int h = (lane * PER) / C;
    float coef = w[(size_t)wid * H + h] / (den[(size_t)d * H + h] + 1e-16f);
    const float* sp = hsrc + (size_t)s * F + lane * PER;
    float* dp = out + (size_t)d * F + lane * PER;
    if (PER == 8) {
        float4 v0 = *(const float4*)sp;
        float4 v1 = *(const float4*)(sp + 4);
        asm volatile("red.global.add.v4.f32 [%0], {%1,%2,%3,%4};" ::
                     "l"(dp), "f"(v0.x * coef), "f"(v0.y * coef),
                     "f"(v0.z * coef), "f"(v0.w * coef) : "memory");
        asm volatile("red.global.add.v4.f32 [%0], {%1,%2,%3,%4};" ::
                     "l"(dp + 4), "f"(v1.x * coef), "f"(v1.y * coef),
                     "f"(v1.z * coef), "f"(v1.w * coef) : "memory");
    } else {
        float2 v = *(const float2*)sp;
        asm volatile("red.global.add.v2.f32 [%0], {%1,%2};" ::
                     "l"(dp), "f"(v.x * coef), "f"(v.y * coef) : "memory");
    }
}

// ---------------- bias (+ optional ELU), vectorized ----------------
template <int F, bool ELU>
__global__ void finalize_kernel(float* __restrict__ acc, const float* __restrict__ b) {
    int i = blockIdx.x * blockDim.x + threadIdx.x;
    if (i >= N_NODES * F / 4) return;
    float4 v = ((float4*)acc)[i];
    int c = (i * 4) & (F - 1);
    v.x += b[c + 0]; v.y += b[c + 1]; v.z += b[c + 2]; v.w += b[c + 3];
    if (ELU) {
        v.x = v.x > 0.f ? v.x : expm1f(v.x);
        v.y = v.y > 0.f ? v.y : expm1f(v.y);
        v.z = v.z > 0.f ? v.z : expm1f(v.z);
        v.w = v.w > 0.f ? v.w : expm1f(v.w);
    }
    ((float4*)acc)[i] = v;
}

// ---------------- launch ----------------
extern "C" void kernel_launch(void* const* d_in, const int* in_sizes, int n_in,
                              void* d_out, int out_size) {
    const float* x   = (const float*)d_in[0];
    const int*   ei  = (const int*)d_in[1];
    const float* ea  = (const float*)d_in[2];
    const float* W1  = (const float*)d_in[3];
    const float* We1 = (const float*)d_in[4];
    const float* as1 = (const float*)d_in[5];
    const float* ad1 = (const float*)d_in[6];
    const float* ae1 = (const float*)d_in[7];
    const float* b1  = (const float*)d_in[8];
    const float* W2  = (const float*)d_in[9];
    const float* We2 = (const float*)d_in[10];
    const float* as2 = (const float*)d_in[11];
    const float* ad2 = (const float*)d_in[12];
    const float* ae2 = (const float*)d_in[13];
    const float* b2  = (const float*)d_in[14];
    float* out = (float*)d_out;

    void* p;
    #define SYM(var, sym) cudaGetSymbolAddress(&p, sym); auto* var = (decltype(&sym[0]))p
    SYM(h1, g_h1);     SYM(out1, g_out1);   SYM(h2, g_h2);
    SYM(ssrc1, g_ssrc1); SYM(sdst1, g_sdst1);
    SYM(ssrc2, g_ssrc2); SYM(sdst2, g_sdst2);
    SYM(m1, g_m1);     SYM(den1, g_den1);
    SYM(m2, g_m2);     SYM(den2, g_den2);
    SYM(al1, g_alpha1); SYM(al2, g_alpha2);
    SYM(la, g_loop);   SYM(cnt, g_cnt);     SYM(asum, g_asum);
    SYM(ce1, g_ce1);   SYM(ce2, g_ce2);
    #undef SYM

    const int NB_N   = (N_NODES + 255) / 256;          // 196
    const int NB_E   = (N_EDGES + 255) / 256;          // 1954
    const int NB_E2  = (E2 + 255) / 256;               // 2149
    const int NB_W   = (E2 * 32 + 255) / 256;          // warp-per-edge
    const int NB_NW  = (N_NODES * 32 + 255) / 256;     // warp-per-node
    const int GB_M   = (N_NODES + 63) / 64;            // 782

    // --- self-loop attr (computed once, reused by both layers) ---
    init_pre<<<NB_N, 256>>>(cnt, asum);
    edge_stats<<<NB_E, 256>>>(ei, ea, cnt, asum);
    loop_attr_kernel<<<NB_N, 256>>>(cnt, asum, la);

    // --- layer 1 ---
    gemm_kernel<IN_DIM, F1><<<dim3(GB_M, F1 / 64), 256>>>(x, W1, h1);
    score_kernel<HH1, CC1><<<NB_NW, 256>>>(h1, as1, ad1, ssrc1, sdst1);
    ce_kernel<HH1, CC1><<<1, 32 * HH1>>>(We1, ae1, ce1);
    init_layer<<<(N_NODES * F1 / 4 + 255) / 256, 256>>>(out1, N_NODES * F1 / 4, m1, den1, N_NODES * HH1);
    edge_max<HH1><<<NB_E2, 256>>>(ei, ea, ssrc1, sdst1, ce1, la, al1, m1);
    edge_sumexp<HH1><<<NB_E2, 256>>>(ei, al1, m1, den1);
    edge_agg<HH1, CC1><<<NB_W, 256>>>(ei, al1, den1, h1, out1);
    finalize_kernel<F1, true><<<(N_NODES * F1 / 4 + 255) / 256, 256>>>(out1, b1);

    // --- layer 2 ---
    gemm_kernel<F1, F2><<<dim3(GB_M, F2 / 64), 256>>>(out1, W2, h2);
    score_kernel<HH2, CC2><<<NB_NW, 256>>>(h2, as2, ad2, ssrc2, sdst2);
    ce_kernel<HH2, CC2><<<1, 32 * HH2>>>(We2, ae2, ce2);
    init_layer<<<(N_NODES * F2 / 4 + 255) / 256, 256>>>(out, N_NODES * F2 / 4, m2, den2, N_NODES * HH2);
    edge_max<HH2><<<NB_E2, 256>>>(ei, ea, ssrc2, sdst2, ce2, la, al2, m2);
    edge_sumexp<HH2><<<NB_E2, 256>>>(ei, al2, m2, den2);
    edge_agg<HH2, CC2><<<NB_W, 256>>>(ei, al2, den2, h2, out);
    finalize_kernel<F2, false><<<(N_NODES * F2 / 4 + 255) / 256, 256>>>(out, b2);
}

// round 4
// speedup vs baseline: 1.7123x; 1.7123x over previous
#include <cuda_runtime.h>
#include <math.h>

#define N_NODES 50000
#define N_EDGES 500000
#define E2 (N_EDGES + N_NODES)   // edges + self loops
#define IN_DIM 128
#define F1 256
#define HH1 4
#define CC1 64
#define F2 64
#define HH2 1
#define CC2 64
#define NBLK_N 196               // ceil(50000/256)

// ---------------- scratch (static device globals; no allocation) ----------------
__device__ float g_h1[(size_t)N_NODES * F1];
__device__ float g_out1[(size_t)N_NODES * F1];
__device__ float g_h2[(size_t)N_NODES * F2];
__device__ float g_ssrc1[N_NODES * HH1];
__device__ float g_sdst1[N_NODES * HH1];
__device__ float g_ssrc2[N_NODES * HH2];
__device__ float g_sdst2[N_NODES * HH2];
__device__ float g_asum[N_NODES];
__device__ int   g_deg[N_NODES];
__device__ float g_loop[N_NODES];
__device__ int   g_part[N_NODES];
__device__ int   g_bsum[256];
__device__ int   g_off[N_NODES + 1];
__device__ int   g_fill[N_NODES];
__device__ int   g_csrc[E2];
__device__ float g_cea[E2];
__device__ float g_ce1[HH1];
__device__ float g_ce2[HH2];

// ---------------- pre: degree + edge-attr stats ----------------
__global__ void init_pre(int* deg, float* asum) {
    int i = blockIdx.x * blockDim.x + threadIdx.x;
    if (i < N_NODES) { deg[i] = 0; asum[i] = 0.f; }
}

__global__ void edge_stats(const int* __restrict__ ei, const float* __restrict__ ea,
                           int* __restrict__ deg, float* __restrict__ asum) {
    int j = blockIdx.x * blockDim.x + threadIdx.x;
    if (j >= N_EDGES) return;
    int d = ei[N_EDGES + j];
    atomicAdd(&deg[d], 1);
    atomicAdd(&asum[d], ea[j]);
}

__global__ void loop_attr_kernel(const int* __restrict__ deg, const float* __restrict__ asum,
                                 float* __restrict__ la) {
    int i = blockIdx.x * blockDim.x + threadIdx.x;
    if (i < N_NODES) la[i] = asum[i] / fmaxf((float)deg[i], 1.f);
}

// ---------------- 3-kernel exclusive scan of (deg+1) -> CSR offsets ----------------
__global__ void scan_block(const int* __restrict__ deg, int* __restrict__ part,
                           int* __restrict__ bsum) {
    __shared__ int sh[256];
    int i = blockIdx.x * 256 + threadIdx.x;
    int v = (i < N_NODES) ? deg[i] + 1 : 0;
    sh[threadIdx.x] = v;
    __syncthreads();
    for (int o = 1; o < 256; o <<= 1) {
        int t = (threadIdx.x >= o) ? sh[threadIdx.x - o] : 0;
        __syncthreads();
        sh[threadIdx.x] += t;
        __syncthreads();
    }
    if (i < N_NODES) part[i] = sh[threadIdx.x] - v;   // exclusive within block
    if (threadIdx.x == 255) bsum[blockIdx.x] = sh[255];
}

__global__ void scan_tops(int* bsum) {  // 1 block, 256 threads; NBLK_N <= 256
    __shared__ int sh[256];
    int v = (threadIdx.x < NBLK_N) ? bsum[threadIdx.x] : 0;
    sh[threadIdx.x] = v;
    __syncthreads();
    for (int o = 1; o < 256; o <<= 1) {
        int t = (threadIdx.x >= o) ? sh[threadIdx.x - o] : 0;
        __syncthreads();
        sh[threadIdx.x] += t;
        __syncthreads();
    }
    if (threadIdx.x < NBLK_N) bsum[threadIdx.x] = sh[threadIdx.x] - v;  // exclusive
}

__global__ void scan_final(const int* __restrict__ part, const int* __restrict__ bsum,
                           int* __restrict__ off) {
    int i = blockIdx.x * 256 + threadIdx.x;
    if (i < N_NODES) off[i] = part[i] + bsum[blockIdx.x];
    if (i == 0) off[N_NODES] = E2;
}

// ---------------- CSR fill: slot 0 = self loop, then scatter edges ----------------
__global__ void csr_selfloop(const int* __restrict__ off, const float* __restrict__ la,
                             int* __restrict__ csrc, float* __restrict__ cea,
                             int* __restrict__ fill) {
    int i = blockIdx.x * blockDim.x + threadIdx.x;
    if (i >= N_NODES) return;
    int p = off[i];
    csrc[p] = i;
    cea[p] = la[i];
    fill[i] = 1;
}

__global__ void csr_fill(const int* __restrict__ ei, const float* __restrict__ ea,
                         const int* __restrict__ off, int* __restrict__ fill,
                         int* __restrict__ csrc, float* __restrict__ cea) {
    int j = blockIdx.x * blockDim.x + threadIdx.x;
    if (j >= N_EDGES) return;
    int d = ei[N_EDGES + j];
    int p = off[d] + atomicAdd(&fill[d], 1);
    csrc[p] = ei[j];
    cea[p] = ea[j];
}

// ---------------- GEMM: C[M,NC] = A[M,K] @ B[K,NC]; BM=128, BK=32, TM=8 ----------------
template <int K, int NC, int BN, int TN>
__global__ __launch_bounds__(256) void gemm_kernel(const float* __restrict__ A,
                                                   const float* __restrict__ B,
                                                   float* __restrict__ C) {
    const int BM = 128, BK = 32, TM = 8;
    const int TX = BN / TN;  // 16
    __shared__ float As[BK][BM + 4];  // [k][m]
    __shared__ float Bs[BK][BN];      // [k][c]

    const int tid = threadIdx.x;
    const int tx = tid % TX, ty = tid / TX;
    const int mbase = blockIdx.x * BM, cbase = blockIdx.y * BN;

    float acc[TM][TN] = {};

    for (int kc = 0; kc < K; kc += BK) {
        // stage A (transposed): BM*BK/4 = 1024 float4; 4 per thread
        #pragma unroll
        for (int r = 0; r < (BM * BK / 4) / 256; r++) {
            int f = tid + r * 256;
            int row = f >> 3, kq = f & 7;
            int gm = mbase + row;
            float4 v = make_float4(0.f, 0.f, 0.f, 0.f);
            if (gm < N_NODES) v = *(const float4*)(A + (size_t)gm * K + kc + kq * 4);
            As[kq * 4 + 0][row] = v.x;
            As[kq * 4 + 1][row] = v.y;
            As[kq * 4 + 2][row] = v.z;
            As[kq * 4 + 3][row] = v.w;
        }
        // stage B direct
        #pragma unroll
        for (int r = 0; r < (BK * BN / 4) / 256; r++) {
            int f = tid + r * 256;
            int c4 = f % (BN / 4), kr = f / (BN / 4);
            *(float4*)&Bs[kr][c4 * 4] =
                *(const float4*)(B + (size_t)(kc + kr) * NC + cbase + c4 * 4);
        }
        __syncthreads();
        #pragma unroll
        for (int k = 0; k < BK; k++) {
            float a[TM], b[TN];
            #pragma unroll
            for (int i = 0; i < TM; i += 4) *(float4*)&a[i] = *(const float4*)&As[k][ty * TM + i];
            #pragma unroll
            for (int j = 0; j < TN; j += 4) *(float4*)&b[j] = *(const float4*)&Bs[k][tx * TN + j];
            #pragma unroll
            for (int i = 0; i < TM; i++)
                #pragma unroll
                for (int j = 0; j < TN; j++) acc[i][j] += a[i] * b[j];
        }
        __syncthreads();
    }

    #pragma unroll
    for (int i = 0; i < TM; i++) {
        int gm = mbase + ty * TM + i;
        if (gm < N_NODES) {
            #pragma unroll
            for (int j = 0; j < TN; j += 4)
                *(float4*)(C + (size_t)gm * NC + cbase + tx * TN + j) =
                    make_float4(acc[i][j], acc[i][j + 1], acc[i][j + 2], acc[i][j + 3]);
        }
    }
}

// ---------------- per-node attention scores ----------------
template <int H, int C>
__global__ void score_kernel(const float* __restrict__ h, const float* __restrict__ a_src,
                             const float* __restrict__ a_dst,
                             float* __restrict__ ssrc, float* __restrict__ sdst) {
    const int F = H * C;
    const int PER = F / 32;
    const int G = 32 / H;
    int node = (blockIdx.x * blockDim.x + threadIdx.x) >> 5;
    int lane = threadIdx.x & 31;
    if (node >= N_NODES) return;

    float ps = 0.f, pd = 0.f;
    #pragma unroll
    for (int j = 0; j < PER; j++) {
        int f = lane * PER + j;
        float hv = h[(size_t)node * F + f];
        ps += hv * a_src[f];
        pd += hv * a_dst[f];
    }
    #pragma unroll
    for (int off = G / 2; off > 0; off >>= 1) {
        ps += __shfl_xor_sync(0xFFFFFFFFu, ps, off);
        pd += __shfl_xor_sync(0xFFFFFFFFu, pd, off);
    }
    if ((lane & (G - 1)) == 0) {
        int hd = lane / G;
        ssrc[node * H + hd] = ps;
        sdst[node * H + hd] = pd;
    }
}

// ---------------- ce[h] = dot(We[h*C..], ae[h*C..]) ----------------
template <int H, int C>
__global__ void ce_kernel(const float* __restrict__ We, const float* __restrict__ ae,
                          float* __restrict__ ce) {
    int h = threadIdx.x >> 5;
    int lane = threadIdx.x & 31;
    float s = 0.f;
    for (int c = lane; c < C; c += 32) s += We[h * C + c] * ae[h * C + c];
    #pragma unroll
    for (int off = 16; off > 0; off >>= 1) s += __shfl_xor_sync(0xFFFFFFFFu, s, off);
    if (lane == 0) ce[h] = s;
}

// ---------------- fused softmax + aggregation + bias(+ELU): warp per dst node ----------------
template <int H, int C, bool ELU>
__global__ __launch_bounds__(256) void node_agg(
    const int* __restrict__ off, const int* __restrict__ csrc, const float* __restrict__ cea,
    const float* __restrict__ ssrc, const float* __restrict__ sdst, const float* __restrict__ ce,
    const float* __restrict__ hfeat, const float* __restrict__ bias, float* __restrict__ out) {
    const int F = H * C, PER = F / 32;
    int d = (blockIdx.x * blockDim.x + threadIdx.x) >> 5;
    int lane = threadIdx.x & 31;
    if (d >= N_NODES) return;

    int e0 = off[d], e1 = off[d + 1];

    float sd[H], cv[H];
    #pragma unroll
    for (int h = 0; h < H; h++) { sd[h] = sdst[(size_t)d * H + h]; cv[h] = ce[h]; }

    // phase 1: online softmax (max + denom) over this node's edges
    float m[H], ss[H];
    #pragma unroll
    for (int h = 0; h < H; h++) { m[h] = -1e30f; ss[h] = 0.f; }

    for (int e = e0 + lane; e < e1; e += 32) {
        int s = csrc[e];
        float a = cea[e];
        float sv[H];
        if (H == 4) {
            float4 t = *(const float4*)(ssrc + (size_t)s * 4);
            sv[0] = t.x; sv[1] = t.y; sv[2] = t.z; sv[3] = t.w;
        } else {
            sv[0] = ssrc[s];
        }
        #pragma unroll
        for (int h = 0; h < H; h++) {
            float v = sv[h] + sd[h] + a * cv[h];
            v = (v >= 0.f) ? v : 0.2f * v;
            float nm = fmaxf(m[h], v);
            ss[h] = ss[h] * __expf(m[h] - nm) + __expf(v - nm);
            m[h] = nm;
        }
    }
    #pragma unroll
    for (int o = 16; o > 0; o >>= 1) {
        #pragma unroll
        for (int h = 0; h < H; h++) {
            float m2 = __shfl_xor_sync(0xFFFFFFFFu, m[h], o);
            float s2 = __shfl_xor_sync(0xFFFFFFFFu, ss[h], o);
            float nm = fmaxf(m[h], m2);
            ss[h] = ss[h] * __expf(m[h] - nm) + s2 * __expf(m2 - nm);
            m[h] = nm;
        }
    }

    // select this lane's head constants (compile-time unrolled, no local-mem indexing)
    const int hme = (lane * PER) / C;
    float my_m = m[0], my_s = ss[0], my_sd = sd[0], my_ce = cv[0];
    #pragma unroll
    for (int h = 1; h < H; h++)
        if (hme == h) { my_m = m[h]; my_s = ss[h]; my_sd = sd[h]; my_ce = cv[h]; }
    float inv = 1.f / (my_s + 1e-16f);

    // phase 2: weighted gather-accumulate (whole warp per edge)
    float acc[PER];
    #pragma unroll
    for (int i = 0; i < PER; i++) acc[i] = 0.f;

    for (int e = e0; e < e1; e++) {
        int s = csrc[e];
        float a = cea[e];
        float v = ssrc[(size_t)s * H + hme] + my_sd + a * my_ce;
        v = (v >= 0.f) ? v : 0.2f * v;
        float coef = __expf(v - my_m) * inv;
        const float* sp = hfeat + (size_t)s * F + lane * PER;
        if (PER == 8) {
            float4 v0 = *(const float4*)sp;
            float4 v1 = *(const float4*)(sp + 4);
            acc[0] += coef * v0.x; acc[1] += coef * v0.y;
            acc[2] += coef * v0.z; acc[3] += coef * v0.w;
            acc[4] += coef * v1.x; acc[5] += coef * v1.y;
            acc[6] += coef * v1.z; acc[7] += coef * v1.w;
        } else {
            float2 v0 = *(const float2*)sp;
            acc[0] += coef * v0.x; acc[1] += coef * v0.y;
        }
    }

    // epilogue: bias (+ELU), single plain store
    float* op = out + (size_t)d * F + lane * PER;
    #pragma unroll
    for (int i = 0; i < PER; i++) {
        float v = acc[i] + bias[lane * PER + i];
        if (ELU) v = (v > 0.f) ? v : expm1f(v);
        op[i] = v;
    }
}

// ---------------- launch ----------------
extern "C" void kernel_launch(void* const* d_in, const int* in_sizes, int n_in,
                              void* d_out, int out_size) {
    const float* x   = (const float*)d_in[0];
    const int*   ei  = (const int*)d_in[1];
    const float* ea  = (const float*)d_in[2];
    const float* W1  = (const float*)d_in[3];
    const float* We1 = (const float*)d_in[4];
    const float* as1 = (const float*)d_in[5];
    const float* ad1 = (const float*)d_in[6];
    const float* ae1 = (const float*)d_in[7];
    const float* b1  = (const float*)d_in[8];
    const float* W2  = (const float*)d_in[9];
    const float* We2 = (const float*)d_in[10];
    const float* as2 = (const float*)d_in[11];
    const float* ad2 = (const float*)d_in[12];
    const float* ae2 = (const float*)d_in[13];
    const float* b2  = (const float*)d_in[14];
    float* out = (float*)d_out;

    void* p;
    #define SYM(var, sym) cudaGetSymbolAddress(&p, sym); auto* var = (decltype(&sym[0]))p
    SYM(h1, g_h1);       SYM(out1, g_out1);   SYM(h2, g_h2);
    SYM(ssrc1, g_ssrc1); SYM(sdst1, g_sdst1);
    SYM(ssrc2, g_ssrc2); SYM(sdst2, g_sdst2);
    SYM(asum, g_asum);   SYM(deg, g_deg);     SYM(la, g_loop);
    SYM(part, g_part);   SYM(bsum, g_bsum);   SYM(off, g_off);
    SYM(fill, g_fill);   SYM(csrc, g_csrc);   SYM(cea, g_cea);
    SYM(ce1, g_ce1);     SYM(ce2, g_ce2);
    #undef SYM

    const int NB_E  = (N_EDGES + 255) / 256;
    const int NB_NW = (N_NODES * 32 + 255) / 256;  // warp-per-node kernels
    const int GB_M  = (N_NODES + 127) / 128;       // 391

    // --- CSR build (degree -> scan -> scatter; self-loop at slot 0) ---
    init_pre<<<NBLK_N, 256>>>(deg, asum);
    edge_stats<<<NB_E, 256>>>(ei, ea, deg, asum);
    loop_attr_kernel<<<NBLK_N, 256>>>(deg, asum, la);
    scan_block<<<NBLK_N, 256>>>(deg, part, bsum);
    scan_tops<<<1, 256>>>(bsum);
    scan_final<<<NBLK_N, 256>>>(part, bsum, off);
    csr_selfloop<<<NBLK_N, 256>>>(off, la, csrc, cea, fill);
    csr_fill<<<NB_E, 256>>>(ei, ea, off, fill, csrc, cea);

    // --- layer 1 ---
    gemm_kernel<IN_DIM, F1, 128, 8><<<dim3(GB_M, F1 / 128), 256>>>(x, W1, h1);
    score_kernel<HH1, CC1><<<NB_NW, 256>>>(h1, as1, ad1, ssrc1, sdst1);
    ce_kernel<HH1, CC1><<<1, 32 * HH1>>>(We1, ae1, ce1);
    node_agg<HH1, CC1, true><<<NB_NW, 256>>>(off, csrc, cea, ssrc1, sdst1, ce1, h1, b1, out1);

    // --- layer 2 ---
    gemm_kernel<F1, F2, 64, 4><<<dim3(GB_M, F2 / 64), 256>>>(out1, W2, h2);
    score_kernel<HH2, CC2><<<NB_NW, 256>>>(h2, as2, ad2, ssrc2, sdst2);
    ce_kernel<HH2, CC2><<<1, 32 * HH2>>>(We2, ae2, ce2);
    node_agg<HH2, CC2, false><<<NB_NW, 256>>>(off, csrc, cea, ssrc2, sdst2, ce2, h2, b2, out);
}